// round 7
// baseline (speedup 1.0000x reference)
#include <cuda_runtime.h>
#include <cuda_bf16.h>
#include <cuda.h>
#include <cstdint>

// ---------------- problem constants ----------------
#define S_LEN 4096
#define NROWS 8192
#define D_IN  7168
#define LORA  1536
#define NH    64
#define DHD   128
#define QN    (NROWS * NH * DHD)
#define WN    (NROWS * NH)
#define KN    (NROWS * DHD)

#define WSCALE 0.011048543456039806f  // (H*DH)^-0.5 (applied in epilogue now)
#define HSCALE 0.08838834764831845f   // 128^-0.5
#define FOLD   3.0517578125e-5f       // 2^-15

// fp8 scales: A-lo x 2^9, B-hi x 2^6, B-lo x 2^15  (product scale 2^15 both terms)
#define SAL 512.0f
#define SBH 64.0f
#define SBL 32768.0f

// ---------------- device scratch ----------------
__device__ __nv_bfloat16 g_qr_h[NROWS * LORA];
__device__ uint8_t       g_qr_8h[NROWS * LORA];
__device__ uint8_t       g_qr_8l[NROWS * LORA];
__device__ __nv_bfloat16 g_wq_h[NROWS * LORA];
__device__ uint8_t       g_wq_8h[NROWS * LORA];
__device__ uint8_t       g_wq_8l[NROWS * LORA];
__device__ __nv_bfloat16 g_x_h[(size_t)NROWS * D_IN];
__device__ uint8_t       g_x_8h[(size_t)NROWS * D_IN];
__device__ uint8_t       g_x_8l[(size_t)NROWS * D_IN];
__device__ __nv_bfloat16 g_wb_h[256 * D_IN];
__device__ uint8_t       g_wb_8h[256 * D_IN];
__device__ uint8_t       g_wb_8l[256 * D_IN];

// ---------------- split helpers ----------------
__device__ __forceinline__ uint32_t pack_bf2(__nv_bfloat16 a, __nv_bfloat16 b) {
    return (uint32_t)__bfloat16_as_ushort(a) | ((uint32_t)__bfloat16_as_ushort(b) << 16);
}
__device__ __forceinline__ uint16_t cvt_e4m3x2(float hi, float lo) {
    uint16_t r;
    asm("cvt.rn.satfinite.e4m3x2.f32 %0, %1, %2;" : "=h"(r) : "f"(hi), "f"(lo));
    return r;
}
__device__ __forceinline__ uint32_t pack_e4m3x4(float a, float b, float c, float d) {
    return (uint32_t)cvt_e4m3x2(b, a) | ((uint32_t)cvt_e4m3x2(d, c) << 16);
}

// A-type: hi bf16, a8h = fp8(v), a8l = fp8(lo*2^9)
__device__ __forceinline__ void splitA(float4 v, uint2& hb, uint32_t& h8, uint32_t& l8) {
    __nv_bfloat16 hx = __float2bfloat16_rn(v.x), hy = __float2bfloat16_rn(v.y);
    __nv_bfloat16 hz = __float2bfloat16_rn(v.z), hw = __float2bfloat16_rn(v.w);
    float lx = v.x - __bfloat162float(hx), ly = v.y - __bfloat162float(hy);
    float lz = v.z - __bfloat162float(hz), lw = v.w - __bfloat162float(hw);
    hb = make_uint2(pack_bf2(hx, hy), pack_bf2(hz, hw));
    h8 = pack_e4m3x4(v.x, v.y, v.z, v.w);
    l8 = pack_e4m3x4(lx * SAL, ly * SAL, lz * SAL, lw * SAL);
}
// B-type: hi bf16, b8h = fp8(v*2^6), b8l = fp8(lo*2^15)
__device__ __forceinline__ void splitB(float4 v, uint2& hb, uint32_t& h8, uint32_t& l8) {
    __nv_bfloat16 hx = __float2bfloat16_rn(v.x), hy = __float2bfloat16_rn(v.y);
    __nv_bfloat16 hz = __float2bfloat16_rn(v.z), hw = __float2bfloat16_rn(v.w);
    float lx = v.x - __bfloat162float(hx), ly = v.y - __bfloat162float(hy);
    float lz = v.z - __bfloat162float(hz), lw = v.w - __bfloat162float(hw);
    hb = make_uint2(pack_bf2(hx, hy), pack_bf2(hz, hw));
    h8 = pack_e4m3x4(v.x * SBH, v.y * SBH, v.z * SBH, v.w * SBH);
    l8 = pack_e4m3x4(lx * SBL, ly * SBL, lz * SBL, lw * SBL);
}

#define N4Q (NROWS * LORA / 4)
#define N4X (NROWS * D_IN / 4)
#define N4B (256 * D_IN / 4)
#define PREP_TOTAL (2 * N4Q + N4X + N4B)

__global__ void prep_all(const float4* __restrict__ qr, const float4* __restrict__ wqb,
                         const float4* __restrict__ x,
                         const float* __restrict__ wk, const float* __restrict__ wp)
{
    int i = blockIdx.x * blockDim.x + threadIdx.x;
    if (i >= PREP_TOTAL) return;
    uint2 hb; uint32_t h8, l8;
    if (i < N4Q) {
        splitA(qr[i], hb, h8, l8);
        ((uint2*)g_qr_h)[i] = hb;
        ((uint32_t*)g_qr_8h)[i] = h8;
        ((uint32_t*)g_qr_8l)[i] = l8;
    } else if (i < 2 * N4Q) {
        int j = i - N4Q;
        splitB(wqb[j], hb, h8, l8);
        ((uint2*)g_wq_h)[j] = hb;
        ((uint32_t*)g_wq_8h)[j] = h8;
        ((uint32_t*)g_wq_8l)[j] = l8;
    } else if (i < 2 * N4Q + N4X) {
        int j = i - 2 * N4Q;
        splitA(x[j], hb, h8, l8);
        ((uint2*)g_x_h)[j] = hb;
        ((uint32_t*)g_x_8h)[j] = h8;
        ((uint32_t*)g_x_8l)[j] = l8;
    } else {
        int j = i - 2 * N4Q - N4X;
        int row = j / (D_IN / 4);
        int c4  = j % (D_IN / 4);
        float4 v;
        if (row < 128)      v = ((const float4*)wk)[row * (D_IN / 4) + c4];
        else if (row < 192) v = ((const float4*)wp)[(row - 128) * (D_IN / 4) + c4];
        else                v = make_float4(0.f, 0.f, 0.f, 0.f);
        splitB(v, hb, h8, l8);
        ((uint2*)g_wb_h)[j] = hb;
        ((uint32_t*)g_wb_8h)[j] = h8;
        ((uint32_t*)g_wb_8l)[j] = l8;
    }
}

// ---------------- PTX helpers ----------------
__device__ __forceinline__ uint32_t elect_one_pred() {
    uint32_t p;
    asm volatile("{\n\t.reg .pred p;\n\telect.sync _|p, 0xFFFFFFFF;\n\tselp.b32 %0, 1, 0, p;\n\t}" : "=r"(p));
    return p;
}
__device__ __forceinline__ uint32_t smem_u32(const void* p) {
    uint32_t a;
    asm("{ .reg .u64 t; cvta.to.shared.u64 t, %1; cvt.u32.u64 %0, t; }" : "=r"(a) : "l"(p));
    return a;
}

#define MBARRIER_INIT(a, c) \
    asm volatile("mbarrier.init.shared.b64 [%0], %1;" :: "r"((uint32_t)(a)), "r"((uint32_t)(c)) : "memory")
#define MBARRIER_EXPECT_TX(a, b) \
    asm volatile("mbarrier.arrive.expect_tx.shared.b64 _, [%0], %1;" :: "r"((uint32_t)(a)), "r"((uint32_t)(b)) : "memory")

#define MBARRIER_WAIT_PARITY(mbar, par) do {                                          \
    uint32_t _m = (uint32_t)(mbar), _p = (uint32_t)(par), _d;                         \
    asm volatile("{\n\t.reg .pred p;\n\t"                                             \
        "mbarrier.try_wait.parity.acquire.cta.shared::cta.b64 p, [%1], %2;\n\t"       \
        "selp.b32 %0, 1, 0, p;\n\t}" : "=r"(_d) : "r"(_m), "r"(_p) : "memory");       \
    if (!_d) {                                                                         \
        asm volatile("{\n\t.reg .pred P1;\n\t"                                        \
            "WL_%=:\n\t"                                                              \
            "mbarrier.try_wait.parity.acquire.cta.shared::cta.b64 P1, [%0], %1, 0x989680;\n\t" \
            "@P1 bra.uni WD_%=;\n\t"                                                  \
            "bra.uni WL_%=;\n\t"                                                      \
            "WD_%=:\n\t}" :: "r"(_m), "r"(_p) : "memory");                            \
    }                                                                                  \
} while (0)

#define TMA_LOAD_3D(sa, tm, cx, cy, cz, mb)                                           \
    asm volatile("cp.async.bulk.tensor.3d.shared::cta.global.tile.mbarrier::complete_tx::bytes " \
        "[%0], [%1, {%2, %3, %4}], [%5];"                                             \
        :: "r"((uint32_t)(sa)), "l"(tm), "r"((int)(cx)), "r"((int)(cy)), "r"((int)(cz)), \
           "r"((uint32_t)(mb)) : "memory")

#define FENCE_PROXY_ASYNC() asm volatile("fence.proxy.async.shared::cta;" ::: "memory")

#define LDSM4(r0, r1, r2, r3, addr)                                              \
    asm volatile("ldmatrix.sync.aligned.m8n8.x4.shared.b16 {%0,%1,%2,%3},[%4];"  \
                 : "=r"(r0), "=r"(r1), "=r"(r2), "=r"(r3) : "r"(addr))

#define MMA_BF16(d, a, b)                                                        \
    asm volatile("mma.sync.aligned.m16n8k16.row.col.f32.bf16.bf16.f32 "          \
                 "{%0,%1,%2,%3},{%4,%5,%6,%7},{%8,%9},{%0,%1,%2,%3};"            \
                 : "+f"((d)[0]), "+f"((d)[1]), "+f"((d)[2]), "+f"((d)[3])        \
                 : "r"((a)[0]), "r"((a)[1]), "r"((a)[2]), "r"((a)[3]),           \
                   "r"((b)[0]), "r"((b)[1]))

#define MMA_FP8(d, a, b)                                                         \
    asm volatile("mma.sync.aligned.m16n8k32.row.col.f32.e4m3.e4m3.f32 "          \
                 "{%0,%1,%2,%3},{%4,%5,%6,%7},{%8,%9},{%0,%1,%2,%3};"            \
                 : "+f"((d)[0]), "+f"((d)[1]), "+f"((d)[2]), "+f"((d)[3])        \
                 : "r"((a)[0]), "r"((a)[1]), "r"((a)[2]), "r"((a)[3]),           \
                   "r"((b)[0]), "r"((b)[1]))

// SW128: bits [6:4] ^= bits [9:7] (128B rows);  SW64: bits [5:4] ^= bits [8:7] (64B rows)
__device__ __forceinline__ uint32_t swz(uint32_t o)   { return o ^ ((o >> 3) & 0x70); }
__device__ __forceinline__ uint32_t swz64(uint32_t o) { return o ^ ((o >> 3) & 0x30); }

// ---------------- smem layout ----------------
// Block tile 128(M) x 256(N), K-chunk 64 elements.
// Stage: AHbf 16K | BHbf 32K | A8H 8K | A8L 8K | B8H 16K | B8L 16K = 96K. 2 stages.
#define CTRL     1024
#define STAGE_B  98304
#define AH_O     0
#define BH_O     16384
#define A8H_O    49152
#define A8L_O    57344
#define B8H_O    65536
#define B8L_O    81920
#define NSTAGE   2
#define SMEM_TOT (CTRL + NSTAGE * STAGE_B)   // 197632

// =====================================================================
// Unified GEMM: main pass bf16 (Ah·Bh), corrections fp8 e4m3
// (Al·Bh + Ah·Bl, folded x2^-15). Tile 128x256, fused epilogues.
// =====================================================================
__global__ __launch_bounds__(256, 1)
void fused_gemm(const __grid_constant__ CUtensorMap mQAh, const __grid_constant__ CUtensorMap mQA8h,
                const __grid_constant__ CUtensorMap mQA8l, const __grid_constant__ CUtensorMap mQBh,
                const __grid_constant__ CUtensorMap mQB8h, const __grid_constant__ CUtensorMap mQB8l,
                const __grid_constant__ CUtensorMap mPAh, const __grid_constant__ CUtensorMap mPA8h,
                const __grid_constant__ CUtensorMap mPA8l, const __grid_constant__ CUtensorMap mPBh,
                const __grid_constant__ CUtensorMap mPB8h, const __grid_constant__ CUtensorMap mPB8l,
                float* __restrict__ qout, float* __restrict__ kout, float* __restrict__ wout,
                const float* __restrict__ fc, const float* __restrict__ fs,
                const float* __restrict__ kg, const float* __restrict__ kb)
{
    extern __shared__ char smem_raw[];
    const uint32_t sb = smem_u32(smem_raw);
    const int tid = threadIdx.x, lane = tid & 31, warp = tid >> 5;
    const int wm = warp >> 2, wn = warp & 3;
    const int tm = wm << 6, tn = wn << 6;     // warp tile 64x64

    const int bid = blockIdx.x;
    const bool proj = (bid < 64);
    int bm, bn, K;
    const CUtensorMap *pAh, *pA8h, *pA8l, *pBh, *pB8h, *pB8l;
    if (proj) {
        bm = bid; bn = 0; K = D_IN;
        pAh = &mPAh; pA8h = &mPA8h; pA8l = &mPA8l;
        pBh = &mPBh; pB8h = &mPB8h; pB8l = &mPB8l;
    } else {
        int t = bid - 64;
        bm = t & 63; bn = t >> 6; K = LORA;
        pAh = &mQAh; pA8h = &mQA8h; pA8l = &mQA8l;
        pBh = &mQBh; pB8h = &mQB8h; pB8l = &mQB8l;
    }
    const int niter = K >> 6;

    if (tid == 0) {
        MBARRIER_INIT(sb + 0, 1);
        MBARRIER_INIT(sb + 8, 1);
        FENCE_PROXY_ASYNC();
    }
    __syncthreads();

    const bool producer = (warp == 0) && elect_one_pred();

    if (producer) {
        #pragma unroll
        for (int p = 0; p < NSTAGE; ++p) {
            const uint32_t fb = sb + p * 8;
            MBARRIER_EXPECT_TX(fb, STAGE_B);
            const uint32_t tb = sb + CTRL + p * STAGE_B;
            const int kt = p << 6;
            TMA_LOAD_3D(tb + AH_O,  pAh,  kt, bm * 128, 0, fb);
            TMA_LOAD_3D(tb + BH_O,  pBh,  kt, bn * 256, 0, fb);
            TMA_LOAD_3D(tb + A8H_O, pA8h, kt, bm * 128, 0, fb);
            TMA_LOAD_3D(tb + A8L_O, pA8l, kt, bm * 128, 0, fb);
            TMA_LOAD_3D(tb + B8H_O, pB8h, kt, bn * 256, 0, fb);
            TMA_LOAD_3D(tb + B8L_O, pB8l, kt, bn * 256, 0, fb);
        }
    }

    float acc[4][8][4] = {};
    int fph[NSTAGE] = {0, 0};

    int s = 0;
    for (int it = 0; it < niter; ++it) {
        MBARRIER_WAIT_PARITY(sb + s * 8, fph[s]);
        fph[s] ^= 1;
        const uint32_t tb = sb + CTRL + s * STAGE_B;

        // ---------- main bf16 pass: Ah · Bh ----------
        #pragma unroll
        for (int s2 = 0; s2 < 4; ++s2) {
            const uint32_t kbyte = s2 << 5;
            uint32_t bhf[8][2];
            {
                const int g = lane >> 3;
                #pragma unroll
                for (int p = 0; p < 4; ++p) {
                    const int row = tn + (((p << 1) + (g >> 1)) << 3) + (lane & 7);
                    const uint32_t off = swz(row * 128 + kbyte + ((g & 1) << 4));
                    LDSM4(bhf[2*p][0], bhf[2*p][1], bhf[2*p+1][0], bhf[2*p+1][1], tb + BH_O + off);
                }
            }
            uint32_t a[4][4];
            #pragma unroll
            for (int i = 0; i < 4; ++i) {
                const int row = tm + (i << 4) + (lane & 15);
                const uint32_t off = swz(row * 128 + kbyte + ((lane >> 4) << 4));
                LDSM4(a[i][0], a[i][1], a[i][2], a[i][3], tb + AH_O + off);
            }
            #pragma unroll
            for (int i = 0; i < 4; ++i)
                #pragma unroll
                for (int j = 0; j < 8; ++j)
                    MMA_BF16(acc[i][j], a[i], bhf[j]);
        }

        // ---------- fp8 correction pass: Al·Bh + Ah·Bl (scale 2^15) ----------
        #pragma unroll
        for (int jh = 0; jh < 2; ++jh)
            #pragma unroll
            for (int ih = 0; ih < 2; ++ih) {
                float cc[2][4][4] = {};
                #pragma unroll
                for (int s8 = 0; s8 < 2; ++s8) {
                    const uint32_t kb8 = s8 << 5;
                    uint32_t bh8[4][2], bl8[4][2];
                    #pragma unroll
                    for (int p = 0; p < 2; ++p) {
                        const int gp = jh * 2 + p;
                        const int row = tn + gp * 16 + ((lane >> 4) << 3) + (lane & 7);
                        const uint32_t off = swz64(row * 64 + (((lane >> 3) & 1) << 4) + kb8);
                        LDSM4(bh8[2*p][0], bh8[2*p][1], bh8[2*p+1][0], bh8[2*p+1][1], tb + B8H_O + off);
                        LDSM4(bl8[2*p][0], bl8[2*p][1], bl8[2*p+1][0], bl8[2*p+1][1], tb + B8L_O + off);
                    }
                    uint32_t a8h2[2][4], a8l2[2][4];
                    #pragma unroll
                    for (int ii = 0; ii < 2; ++ii) {
                        const int i = ih * 2 + ii;
                        const int row = tm + (i << 4) + (lane & 15);
                        const uint32_t off = swz64(row * 64 + ((lane >> 4) << 4) + kb8);
                        LDSM4(a8h2[ii][0], a8h2[ii][1], a8h2[ii][2], a8h2[ii][3], tb + A8H_O + off);
                        LDSM4(a8l2[ii][0], a8l2[ii][1], a8l2[ii][2], a8l2[ii][3], tb + A8L_O + off);
                    }
                    #pragma unroll
                    for (int ii = 0; ii < 2; ++ii)
                        #pragma unroll
                        for (int j = 0; j < 4; ++j) {
                            MMA_FP8(cc[ii][j], a8l2[ii], bh8[j]);
                            MMA_FP8(cc[ii][j], a8h2[ii], bl8[j]);
                        }
                }
                #pragma unroll
                for (int ii = 0; ii < 2; ++ii)
                    #pragma unroll
                    for (int j = 0; j < 4; ++j)
                        #pragma unroll
                        for (int r = 0; r < 4; ++r)
                            acc[ih*2+ii][jh*4+j][r] += cc[ii][j][r] * FOLD;
            }

        __syncthreads();
        if (producer && it + NSTAGE < niter) {
            const uint32_t fb = sb + s * 8;
            MBARRIER_EXPECT_TX(fb, STAGE_B);
            const int kt = (it + NSTAGE) << 6;
            TMA_LOAD_3D(tb + AH_O,  pAh,  kt, bm * 128, 0, fb);
            TMA_LOAD_3D(tb + BH_O,  pBh,  kt, bn * 256, 0, fb);
            TMA_LOAD_3D(tb + A8H_O, pA8h, kt, bm * 128, 0, fb);
            TMA_LOAD_3D(tb + A8L_O, pA8l, kt, bm * 128, 0, fb);
            TMA_LOAD_3D(tb + B8H_O, pB8h, kt, bn * 256, 0, fb);
            TMA_LOAD_3D(tb + B8L_O, pB8l, kt, bn * 256, 0, fb);
        }
        if (++s == NSTAGE) s = 0;
    }

    // ================= fused epilogue =================
    __syncthreads();
    float* tile = reinterpret_cast<float*>(smem_raw + CTRL);   // [128][264]
    #pragma unroll
    for (int i = 0; i < 4; ++i)
        #pragma unroll
        for (int j = 0; j < 8; ++j) {
            const int r0 = tm + (i << 4) + (lane >> 2);
            const int c0 = tn + (j << 3) + ((lane & 3) << 1);
            tile[r0 * 264 + c0]           = acc[i][j][0];
            tile[r0 * 264 + c0 + 1]       = acc[i][j][1];
            tile[(r0 + 8) * 264 + c0]     = acc[i][j][2];
            tile[(r0 + 8) * 264 + c0 + 1] = acc[i][j][3];
        }
    __syncthreads();

    for (int rr = 0; rr < 16; ++rr) {
        const int row = warp * 16 + rr;
        const int grow = bm * 128 + row;
        const float* tr = tile + row * 264;
        const int pos = grow & (S_LEN - 1);
        const float c = fc[pos * 32 + lane];
        const float sn = fs[pos * 32 + lane];

        #pragma unroll
        for (int h = 0; h < 2; ++h) {
            if (proj && h == 1) {
                // weights: cols 128..191, apply WSCALE here
                wout[(size_t)grow * 64 + lane]      = tr[128 + lane] * WSCALE;
                wout[(size_t)grow * 64 + lane + 32] = tr[160 + lane] * WSCALE;
                break;
            }
            float v0 = tr[h*128 + lane],      v1 = tr[h*128 + lane + 32];
            float v2 = tr[h*128 + lane + 64], v3 = tr[h*128 + lane + 96];

            if (proj) {
                float sum = v0 + v1 + v2 + v3;
                float sq  = v0*v0 + v1*v1 + v2*v2 + v3*v3;
                #pragma unroll
                for (int o = 16; o; o >>= 1) {
                    sum += __shfl_xor_sync(0xffffffffu, sum, o);
                    sq  += __shfl_xor_sync(0xffffffffu, sq,  o);
                }
                const float mu  = sum * (1.f / 128.f);
                const float var = sq * (1.f / 128.f) - mu * mu;
                const float r   = rsqrtf(var + 1e-5f);
                v0 = (v0 - mu) * r * kg[lane]      + kb[lane];
                v1 = (v1 - mu) * r * kg[lane + 32] + kb[lane + 32];
                v2 = (v2 - mu) * r * kg[lane + 64] + kb[lane + 64];
                v3 = (v3 - mu) * r * kg[lane + 96] + kb[lane + 96];
            }

            const float x1 = v0, x2 = v1;
            v0 = x1 * c - x2 * sn;
            v1 = x1 * sn + x2 * c;

            #pragma unroll
            for (int st = 1; st < 32; st <<= 1) {
                float p0 = __shfl_xor_sync(0xffffffffu, v0, st);
                float p1 = __shfl_xor_sync(0xffffffffu, v1, st);
                float p2 = __shfl_xor_sync(0xffffffffu, v2, st);
                float p3 = __shfl_xor_sync(0xffffffffu, v3, st);
                if (lane & st) { v0 = p0 - v0; v1 = p1 - v1; v2 = p2 - v2; v3 = p3 - v3; }
                else           { v0 += p0;     v1 += p1;     v2 += p2;     v3 += p3;     }
            }
            float t0 = v0 + v1, t1 = v0 - v1, t2 = v2 + v3, t3 = v2 - v3;
            v0 = t0 + t2; v2 = t0 - t2; v1 = t1 + t3; v3 = t1 - t3;

            if (proj) {
                float* ob = kout + (size_t)grow * 128;
                ob[lane]      = v0 * HSCALE;
                ob[lane + 32] = v1 * HSCALE;
                ob[lane + 64] = v2 * HSCALE;
                ob[lane + 96] = v3 * HSCALE;
            } else {
                float* ob = qout + (size_t)grow * 8192 + bn * 256 + h * 128;
                ob[lane]      = v0 * HSCALE;
                ob[lane + 32] = v1 * HSCALE;
                ob[lane + 64] = v2 * HSCALE;
                ob[lane + 96] = v3 * HSCALE;
            }
        }
    }
}

__global__ void write_end(float* __restrict__ eout, const int* __restrict__ sp)
{
    *eout = (float)(*sp + S_LEN);
}

// =====================================================================
typedef CUresult (*EncodeFn)(CUtensorMap*, CUtensorMapDataType, cuuint32_t, void*,
                             const cuuint64_t*, const cuuint64_t*, const cuuint32_t*,
                             const cuuint32_t*, CUtensorMapInterleave, CUtensorMapSwizzle,
                             CUtensorMapL2promotion, CUtensorMapFloatOOBfill);

static void make_map_bf16(EncodeFn enc, CUtensorMap* m, void* base, int K, int R, int boxR)
{
    cuuint64_t dims[3]    = {(cuuint64_t)K, (cuuint64_t)R, 1};
    cuuint64_t strides[2] = {(cuuint64_t)K * 2, (cuuint64_t)K * 2 * (cuuint64_t)R};
    cuuint32_t box[3]     = {64, (cuuint32_t)boxR, 1};
    cuuint32_t es[3]      = {1, 1, 1};
    enc(m, CU_TENSOR_MAP_DATA_TYPE_BFLOAT16, 3, base, dims, strides, box, es,
        CU_TENSOR_MAP_INTERLEAVE_NONE, CU_TENSOR_MAP_SWIZZLE_128B,
        CU_TENSOR_MAP_L2_PROMOTION_L2_128B, CU_TENSOR_MAP_FLOAT_OOB_FILL_NONE);
}
static void make_map_fp8(EncodeFn enc, CUtensorMap* m, void* base, int K, int R, int boxR)
{
    cuuint64_t dims[3]    = {(cuuint64_t)K, (cuuint64_t)R, 1};
    cuuint64_t strides[2] = {(cuuint64_t)K, (cuuint64_t)K * (cuuint64_t)R};
    cuuint32_t box[3]     = {64, (cuuint32_t)boxR, 1};
    cuuint32_t es[3]      = {1, 1, 1};
    enc(m, CU_TENSOR_MAP_DATA_TYPE_UINT8, 3, base, dims, strides, box, es,
        CU_TENSOR_MAP_INTERLEAVE_NONE, CU_TENSOR_MAP_SWIZZLE_64B,
        CU_TENSOR_MAP_L2_PROMOTION_L2_128B, CU_TENSOR_MAP_FLOAT_OOB_FILL_NONE);
}

extern "C" void kernel_launch(void* const* d_in, const int* in_sizes, int n_in,
                              void* d_out, int out_size)
{
    const float* x   = (const float*)d_in[0];
    const float* qr  = (const float*)d_in[1];
    const float* fc  = (const float*)d_in[2];
    const float* fs  = (const float*)d_in[3];
    const float* wqb = (const float*)d_in[4];
    const float* wk  = (const float*)d_in[5];
    const float* kg  = (const float*)d_in[6];
    const float* kb  = (const float*)d_in[7];
    const float* wp  = (const float*)d_in[8];
    const int*   sp  = (const int*)d_in[9];

    float* out  = (float*)d_out;
    float* qout = out;
    float* wout = out + QN;
    float* kout = out + QN + WN;
    float* eout = out + QN + WN + KN;

    void *qrh, *qr8h, *qr8l, *wqh, *wq8h, *wq8l, *xh, *x8h, *x8l, *wbh, *wb8h, *wb8l;
    cudaGetSymbolAddress(&qrh,  g_qr_h);
    cudaGetSymbolAddress(&qr8h, g_qr_8h);
    cudaGetSymbolAddress(&qr8l, g_qr_8l);
    cudaGetSymbolAddress(&wqh,  g_wq_h);
    cudaGetSymbolAddress(&wq8h, g_wq_8h);
    cudaGetSymbolAddress(&wq8l, g_wq_8l);
    cudaGetSymbolAddress(&xh,   g_x_h);
    cudaGetSymbolAddress(&x8h,  g_x_8h);
    cudaGetSymbolAddress(&x8l,  g_x_8l);
    cudaGetSymbolAddress(&wbh,  g_wb_h);
    cudaGetSymbolAddress(&wb8h, g_wb_8h);
    cudaGetSymbolAddress(&wb8l, g_wb_8l);

    EncodeFn enc = nullptr;
    cudaDriverEntryPointQueryResult qres;
    cudaGetDriverEntryPoint("cuTensorMapEncodeTiled", (void**)&enc, cudaEnableDefault, &qres);

    CUtensorMap mQAh, mQA8h, mQA8l, mQBh, mQB8h, mQB8l;
    CUtensorMap mPAh, mPA8h, mPA8l, mPBh, mPB8h, mPB8l;
    make_map_bf16(enc, &mQAh,  qrh,  LORA, NROWS, 128);
    make_map_fp8 (enc, &mQA8h, qr8h, LORA, NROWS, 128);
    make_map_fp8 (enc, &mQA8l, qr8l, LORA, NROWS, 128);
    make_map_bf16(enc, &mQBh,  wqh,  LORA, NROWS, 256);
    make_map_fp8 (enc, &mQB8h, wq8h, LORA, NROWS, 256);
    make_map_fp8 (enc, &mQB8l, wq8l, LORA, NROWS, 256);
    make_map_bf16(enc, &mPAh,  xh,   D_IN, NROWS, 128);
    make_map_fp8 (enc, &mPA8h, x8h,  D_IN, NROWS, 128);
    make_map_fp8 (enc, &mPA8l, x8l,  D_IN, NROWS, 128);
    make_map_bf16(enc, &mPBh,  wbh,  D_IN, 256, 256);
    make_map_fp8 (enc, &mPB8h, wb8h, D_IN, 256, 256);
    make_map_fp8 (enc, &mPB8l, wb8l, D_IN, 256, 256);

    cudaFuncSetAttribute(fused_gemm, cudaFuncAttributeMaxDynamicSharedMemorySize, SMEM_TOT);

    prep_all<<<(PREP_TOTAL + 255) / 256, 256>>>(
        (const float4*)qr, (const float4*)wqb, (const float4*)x, wk, wp);

    fused_gemm<<<2112, 256, SMEM_TOT>>>(
        mQAh, mQA8h, mQA8l, mQBh, mQB8h, mQB8l,
        mPAh, mPA8h, mPA8l, mPBh, mPB8h, mPB8l,
        qout, kout, wout, fc, fs, kg, kb);

    write_end<<<1, 1>>>(eout, sp);
}

// round 8
// speedup vs baseline: 1.6468x; 1.6468x over previous
#include <cuda_runtime.h>
#include <cuda_bf16.h>
#include <cuda.h>
#include <cstdint>

// ---------------- problem constants ----------------
#define S_LEN 4096
#define NROWS 8192
#define D_IN  7168
#define LORA  1536
#define NH    64
#define DHD   128
#define QN    (NROWS * NH * DHD)
#define WN    (NROWS * NH)
#define KN    (NROWS * DHD)

#define WSCALE 0.011048543456039806f  // (H*DH)^-0.5
#define HSCALE 0.08838834764831845f   // 128^-0.5

// ---------------- device scratch (bf16 hi/lo splits) ----------------
__device__ __nv_bfloat16 g_qr_h[NROWS * LORA];
__device__ __nv_bfloat16 g_qr_l[NROWS * LORA];
__device__ __nv_bfloat16 g_wq_h[NROWS * LORA];
__device__ __nv_bfloat16 g_wq_l[NROWS * LORA];
__device__ __nv_bfloat16 g_x_h[(size_t)NROWS * D_IN];
__device__ __nv_bfloat16 g_x_l[(size_t)NROWS * D_IN];
__device__ __nv_bfloat16 g_wb_h[256 * D_IN];
__device__ __nv_bfloat16 g_wb_l[256 * D_IN];

// ---------------- split helpers ----------------
__device__ __forceinline__ uint32_t pack_bf2(__nv_bfloat16 a, __nv_bfloat16 b) {
    return (uint32_t)__bfloat16_as_ushort(a) | ((uint32_t)__bfloat16_as_ushort(b) << 16);
}
__device__ __forceinline__ void split4(float4 v, uint2& hi, uint2& lo) {
    __nv_bfloat16 hx = __float2bfloat16_rn(v.x);
    __nv_bfloat16 hy = __float2bfloat16_rn(v.y);
    __nv_bfloat16 hz = __float2bfloat16_rn(v.z);
    __nv_bfloat16 hw = __float2bfloat16_rn(v.w);
    __nv_bfloat16 lx = __float2bfloat16_rn(v.x - __bfloat162float(hx));
    __nv_bfloat16 ly = __float2bfloat16_rn(v.y - __bfloat162float(hy));
    __nv_bfloat16 lz = __float2bfloat16_rn(v.z - __bfloat162float(hz));
    __nv_bfloat16 lw = __float2bfloat16_rn(v.w - __bfloat162float(hw));
    hi = make_uint2(pack_bf2(hx, hy), pack_bf2(hz, hw));
    lo = make_uint2(pack_bf2(lx, ly), pack_bf2(lz, lw));
}

#define N4Q (NROWS * LORA / 4)
#define N4X (NROWS * D_IN / 4)
#define N4B (256 * D_IN / 4)
#define PREP_TOTAL (2 * N4Q + N4X + N4B)

__global__ void prep_all(const float4* __restrict__ qr, const float4* __restrict__ wqb,
                         const float4* __restrict__ x,
                         const float* __restrict__ wk, const float* __restrict__ wp)
{
    int i = blockIdx.x * blockDim.x + threadIdx.x;
    if (i >= PREP_TOTAL) return;
    if (i < N4Q) {
        uint2 h, l; split4(qr[i], h, l);
        ((uint2*)g_qr_h)[i] = h; ((uint2*)g_qr_l)[i] = l;
    } else if (i < 2 * N4Q) {
        int j = i - N4Q;
        uint2 h, l; split4(wqb[j], h, l);
        ((uint2*)g_wq_h)[j] = h; ((uint2*)g_wq_l)[j] = l;
    } else if (i < 2 * N4Q + N4X) {
        int j = i - 2 * N4Q;
        uint2 h, l; split4(x[j], h, l);
        ((uint2*)g_x_h)[j] = h; ((uint2*)g_x_l)[j] = l;
    } else {
        int j = i - 2 * N4Q - N4X;
        int row = j / (D_IN / 4);
        int c4  = j % (D_IN / 4);
        float4 v;
        if (row < 128)      v = ((const float4*)wk)[row * (D_IN / 4) + c4];
        else if (row < 192) {
            v = ((const float4*)wp)[(row - 128) * (D_IN / 4) + c4];
            v.x *= WSCALE; v.y *= WSCALE; v.z *= WSCALE; v.w *= WSCALE;
        } else v = make_float4(0.f, 0.f, 0.f, 0.f);
        uint2 h, l; split4(v, h, l);
        ((uint2*)g_wb_h)[j] = h; ((uint2*)g_wb_l)[j] = l;
    }
}

// ---------------- PTX helpers ----------------
__device__ __forceinline__ uint32_t elect_one_pred() {
    uint32_t p;
    asm volatile("{\n\t.reg .pred p;\n\telect.sync _|p, 0xFFFFFFFF;\n\tselp.b32 %0, 1, 0, p;\n\t}" : "=r"(p));
    return p;
}
__device__ __forceinline__ uint32_t smem_u32(const void* p) {
    uint32_t a;
    asm("{ .reg .u64 t; cvta.to.shared.u64 t, %1; cvt.u32.u64 %0, t; }" : "=r"(a) : "l"(p));
    return a;
}

#define MBARRIER_INIT(a, c) \
    asm volatile("mbarrier.init.shared.b64 [%0], %1;" :: "r"((uint32_t)(a)), "r"((uint32_t)(c)) : "memory")
#define MBARRIER_EXPECT_TX(a, b) \
    asm volatile("mbarrier.arrive.expect_tx.shared.b64 _, [%0], %1;" :: "r"((uint32_t)(a)), "r"((uint32_t)(b)) : "memory")
#define MBARRIER_ARRIVE(a) \
    asm volatile("mbarrier.arrive.shared.b64 _, [%0];" :: "r"((uint32_t)(a)) : "memory")

#define MBARRIER_WAIT_PARITY(mbar, par) do {                                          \
    uint32_t _m = (uint32_t)(mbar), _p = (uint32_t)(par), _d;                         \
    asm volatile("{\n\t.reg .pred p;\n\t"                                             \
        "mbarrier.try_wait.parity.acquire.cta.shared::cta.b64 p, [%1], %2;\n\t"       \
        "selp.b32 %0, 1, 0, p;\n\t}" : "=r"(_d) : "r"(_m), "r"(_p) : "memory");       \
    if (!_d) {                                                                         \
        asm volatile("{\n\t.reg .pred P1;\n\t"                                        \
            "WL_%=:\n\t"                                                              \
            "mbarrier.try_wait.parity.acquire.cta.shared::cta.b64 P1, [%0], %1, 0x989680;\n\t" \
            "@P1 bra.uni WD_%=;\n\t"                                                  \
            "bra.uni WL_%=;\n\t"                                                      \
            "WD_%=:\n\t}" :: "r"(_m), "r"(_p) : "memory");                            \
    }                                                                                  \
} while (0)

#define MBARRIER_WAIT_PARITY_RELAXED(mbar, par) do {                                  \
    uint32_t _m = (uint32_t)(mbar), _p = (uint32_t)(par), _d;                         \
    asm volatile("{\n\t.reg .pred p;\n\t"                                             \
        "mbarrier.try_wait.parity.relaxed.cta.shared::cta.b64 p, [%1], %2, 0x989680;\n\t" \
        "selp.b32 %0, 1, 0, p;\n\t}" : "=r"(_d) : "r"(_m), "r"(_p) : "memory");       \
    if (!_d) {                                                                         \
        asm volatile("{\n\t.reg .pred P1;\n\t"                                        \
            "WL_%=:\n\t"                                                              \
            "mbarrier.try_wait.parity.relaxed.cta.shared::cta.b64 P1, [%0], %1, 0x989680;\n\t" \
            "@P1 bra.uni WD_%=;\n\t"                                                  \
            "bra.uni WL_%=;\n\t"                                                      \
            "WD_%=:\n\t}" :: "r"(_m), "r"(_p) : "memory");                            \
    }                                                                                  \
} while (0)

#define TMA_LOAD_3D(sa, tm, cx, cy, cz, mb)                                           \
    asm volatile("cp.async.bulk.tensor.3d.shared::cta.global.tile.mbarrier::complete_tx::bytes " \
        "[%0], [%1, {%2, %3, %4}], [%5];"                                             \
        :: "r"((uint32_t)(sa)), "l"(tm), "r"((int)(cx)), "r"((int)(cy)), "r"((int)(cz)), \
           "r"((uint32_t)(mb)) : "memory")

#define FENCE_PROXY_ASYNC() asm volatile("fence.proxy.async.shared::cta;" ::: "memory")

#define LDSM4(r0, r1, r2, r3, addr)                                              \
    asm volatile("ldmatrix.sync.aligned.m8n8.x4.shared.b16 {%0,%1,%2,%3},[%4];"  \
                 : "=r"(r0), "=r"(r1), "=r"(r2), "=r"(r3) : "r"(addr))

#define MMA_BF16(d, a, b)                                                        \
    asm volatile("mma.sync.aligned.m16n8k16.row.col.f32.bf16.bf16.f32 "          \
                 "{%0,%1,%2,%3},{%4,%5,%6,%7},{%8,%9},{%0,%1,%2,%3};"            \
                 : "+f"((d)[0]), "+f"((d)[1]), "+f"((d)[2]), "+f"((d)[3])        \
                 : "r"((a)[0]), "r"((a)[1]), "r"((a)[2]), "r"((a)[3]),           \
                   "r"((b)[0]), "r"((b)[1]))

// SW128 swizzle: XOR bits [9:7] into bits [6:4] (128B rows)
__device__ __forceinline__ uint32_t swz(uint32_t o) { return o ^ ((o >> 3) & 0x70); }

// ---------------- smem layout ----------------
// Block tile 128(M) x 256(N), K-chunk 64.
// Stage: AH 16K | AL 16K | BH 32K | BL 32K = 96K. 2 stages.
#define CTRL     1024
#define STAGE_B  98304
#define AH_O     0
#define AL_O     16384
#define BH_O     32768
#define BL_O     65536
#define NSTAGE   2
#define SMEM_TOT (CTRL + NSTAGE * STAGE_B)   // 197632 -> 1 CTA/SM
// barriers: full0 @0, full1 @8, empty0 @16, empty1 @24

// =====================================================================
// Unified TMA-fed mma.sync GEMM, tile 128x256, fused epilogues.
// Stage recycling via empty-mbarrier (count 8, one arrive per warp) —
// no per-iteration __syncthreads; warps skew freely across the window.
// =====================================================================
__global__ __launch_bounds__(256, 1)
void fused_gemm(const __grid_constant__ CUtensorMap mQAh, const __grid_constant__ CUtensorMap mQAl,
                const __grid_constant__ CUtensorMap mQBh, const __grid_constant__ CUtensorMap mQBl,
                const __grid_constant__ CUtensorMap mPAh, const __grid_constant__ CUtensorMap mPAl,
                const __grid_constant__ CUtensorMap mPBh, const __grid_constant__ CUtensorMap mPBl,
                float* __restrict__ qout, float* __restrict__ kout, float* __restrict__ wout,
                const float* __restrict__ fc, const float* __restrict__ fs,
                const float* __restrict__ kg, const float* __restrict__ kb)
{
    extern __shared__ char smem_raw[];
    const uint32_t sb = smem_u32(smem_raw);
    const int tid = threadIdx.x, lane = tid & 31, warp = tid >> 5;
    const int wm = warp >> 2, wn = warp & 3;
    const int tm = wm << 6, tn = wn << 6;     // warp tile 64x64

    const int bid = blockIdx.x;
    const bool proj = (bid < 64);
    int bm, bn, K;
    const CUtensorMap *pAh, *pAl, *pBh, *pBl;
    if (proj) {
        bm = bid; bn = 0; K = D_IN;
        pAh = &mPAh; pAl = &mPAl; pBh = &mPBh; pBl = &mPBl;
    } else {
        int t = bid - 64;
        bm = t & 63; bn = t >> 6; K = LORA;
        pAh = &mQAh; pAl = &mQAl; pBh = &mQBh; pBl = &mQBl;
    }
    const int niter = K >> 6;

    if (tid == 0) {
        MBARRIER_INIT(sb + 0, 1);
        MBARRIER_INIT(sb + 8, 1);
        MBARRIER_INIT(sb + 16, 8);   // empty0: one arrive per warp
        MBARRIER_INIT(sb + 24, 8);   // empty1
        FENCE_PROXY_ASYNC();
    }
    __syncthreads();

    const bool producer = (warp == 0) && elect_one_pred();
    const bool wleader  = elect_one_pred();

    if (producer) {
        #pragma unroll
        for (int p = 0; p < NSTAGE; ++p) {
            const uint32_t fb = sb + p * 8;
            MBARRIER_EXPECT_TX(fb, STAGE_B);
            const uint32_t tb = sb + CTRL + p * STAGE_B;
            const int kt = p << 6;
            TMA_LOAD_3D(tb + AH_O, pAh, kt, bm * 128, 0, fb);
            TMA_LOAD_3D(tb + AL_O, pAl, kt, bm * 128, 0, fb);
            TMA_LOAD_3D(tb + BH_O, pBh, kt, bn * 256, 0, fb);
            TMA_LOAD_3D(tb + BL_O, pBl, kt, bn * 256, 0, fb);
        }
    }

    float acc[4][8][4] = {};
    int fph[NSTAGE] = {0, 0};
    int eph[NSTAGE] = {0, 0};

    int s = 0;
    for (int it = 0; it < niter; ++it) {
        MBARRIER_WAIT_PARITY(sb + s * 8, fph[s]);
        fph[s] ^= 1;
        const uint32_t tb = sb + CTRL + s * STAGE_B;

        #pragma unroll
        for (int s2 = 0; s2 < 4; ++s2) {
            const uint32_t kbyte = s2 << 5;
            uint32_t bhf[8][2], blf[8][2];
            {
                const int g = lane >> 3;
                #pragma unroll
                for (int p = 0; p < 4; ++p) {
                    const int row = tn + (((p << 1) + (g >> 1)) << 3) + (lane & 7);
                    const uint32_t off = swz(row * 128 + kbyte + ((g & 1) << 4));
                    LDSM4(bhf[2*p][0], bhf[2*p][1], bhf[2*p+1][0], bhf[2*p+1][1], tb + BH_O + off);
                    LDSM4(blf[2*p][0], blf[2*p][1], blf[2*p+1][0], blf[2*p+1][1], tb + BL_O + off);
                }
            }
            uint32_t a[4][4];
            #pragma unroll
            for (int i = 0; i < 4; ++i) {
                const int row = tm + (i << 4) + (lane & 15);
                const uint32_t off = swz(row * 128 + kbyte + ((lane >> 4) << 4));
                LDSM4(a[i][0], a[i][1], a[i][2], a[i][3], tb + AH_O + off);
            }
            #pragma unroll
            for (int i = 0; i < 4; ++i)
                #pragma unroll
                for (int j = 0; j < 8; ++j) {
                    MMA_BF16(acc[i][j], a[i], bhf[j]);
                    MMA_BF16(acc[i][j], a[i], blf[j]);
                }
            #pragma unroll
            for (int i = 0; i < 4; ++i) {
                const int row = tm + (i << 4) + (lane & 15);
                const uint32_t off = swz(row * 128 + kbyte + ((lane >> 4) << 4));
                LDSM4(a[i][0], a[i][1], a[i][2], a[i][3], tb + AL_O + off);
            }
            #pragma unroll
            for (int i = 0; i < 4; ++i)
                #pragma unroll
                for (int j = 0; j < 8; ++j)
                    MMA_BF16(acc[i][j], a[i], bhf[j]);
        }

        // all LDSMs of this chunk complete (ldmatrix is warp-synchronous):
        // signal stage free — one arrive per warp.
        if (wleader) MBARRIER_ARRIVE(sb + 16 + s * 8);

        if (producer && it + NSTAGE < niter) {
            MBARRIER_WAIT_PARITY_RELAXED(sb + 16 + s * 8, eph[s]);
            eph[s] ^= 1;
            const uint32_t fb = sb + s * 8;
            MBARRIER_EXPECT_TX(fb, STAGE_B);
            const int kt = (it + NSTAGE) << 6;
            TMA_LOAD_3D(tb + AH_O, pAh, kt, bm * 128, 0, fb);
            TMA_LOAD_3D(tb + AL_O, pAl, kt, bm * 128, 0, fb);
            TMA_LOAD_3D(tb + BH_O, pBh, kt, bn * 256, 0, fb);
            TMA_LOAD_3D(tb + BL_O, pBl, kt, bn * 256, 0, fb);
        }
        if (++s == NSTAGE) s = 0;
    }

    // ================= fused epilogue =================
    __syncthreads();
    float* tile = reinterpret_cast<float*>(smem_raw + CTRL);   // [128][264]
    #pragma unroll
    for (int i = 0; i < 4; ++i)
        #pragma unroll
        for (int j = 0; j < 8; ++j) {
            const int r0 = tm + (i << 4) + (lane >> 2);
            const int c0 = tn + (j << 3) + ((lane & 3) << 1);
            tile[r0 * 264 + c0]           = acc[i][j][0];
            tile[r0 * 264 + c0 + 1]       = acc[i][j][1];
            tile[(r0 + 8) * 264 + c0]     = acc[i][j][2];
            tile[(r0 + 8) * 264 + c0 + 1] = acc[i][j][3];
        }
    __syncthreads();

    for (int rr = 0; rr < 16; ++rr) {
        const int row = warp * 16 + rr;
        const int grow = bm * 128 + row;
        const float* tr = tile + row * 264;
        const int pos = grow & (S_LEN - 1);
        const float c = fc[pos * 32 + lane];
        const float sn = fs[pos * 32 + lane];

        #pragma unroll
        for (int h = 0; h < 2; ++h) {
            if (proj && h == 1) {
                wout[(size_t)grow * 64 + lane]      = tr[128 + lane];
                wout[(size_t)grow * 64 + lane + 32] = tr[160 + lane];
                break;
            }
            float v0 = tr[h*128 + lane],      v1 = tr[h*128 + lane + 32];
            float v2 = tr[h*128 + lane + 64], v3 = tr[h*128 + lane + 96];

            if (proj) {
                float sum = v0 + v1 + v2 + v3;
                float sq  = v0*v0 + v1*v1 + v2*v2 + v3*v3;
                #pragma unroll
                for (int o = 16; o; o >>= 1) {
                    sum += __shfl_xor_sync(0xffffffffu, sum, o);
                    sq  += __shfl_xor_sync(0xffffffffu, sq,  o);
                }
                const float mu  = sum * (1.f / 128.f);
                const float var = sq * (1.f / 128.f) - mu * mu;
                const float r   = rsqrtf(var + 1e-5f);
                v0 = (v0 - mu) * r * kg[lane]      + kb[lane];
                v1 = (v1 - mu) * r * kg[lane + 32] + kb[lane + 32];
                v2 = (v2 - mu) * r * kg[lane + 64] + kb[lane + 64];
                v3 = (v3 - mu) * r * kg[lane + 96] + kb[lane + 96];
            }

            const float x1 = v0, x2 = v1;
            v0 = x1 * c - x2 * sn;
            v1 = x1 * sn + x2 * c;

            #pragma unroll
            for (int st = 1; st < 32; st <<= 1) {
                float p0 = __shfl_xor_sync(0xffffffffu, v0, st);
                float p1 = __shfl_xor_sync(0xffffffffu, v1, st);
                float p2 = __shfl_xor_sync(0xffffffffu, v2, st);
                float p3 = __shfl_xor_sync(0xffffffffu, v3, st);
                if (lane & st) { v0 = p0 - v0; v1 = p1 - v1; v2 = p2 - v2; v3 = p3 - v3; }
                else           { v0 += p0;     v1 += p1;     v2 += p2;     v3 += p3;     }
            }
            float t0 = v0 + v1, t1 = v0 - v1, t2 = v2 + v3, t3 = v2 - v3;
            v0 = t0 + t2; v2 = t0 - t2; v1 = t1 + t3; v3 = t1 - t3;

            if (proj) {
                float* ob = kout + (size_t)grow * 128;
                ob[lane]      = v0 * HSCALE;
                ob[lane + 32] = v1 * HSCALE;
                ob[lane + 64] = v2 * HSCALE;
                ob[lane + 96] = v3 * HSCALE;
            } else {
                float* ob = qout + (size_t)grow * 8192 + bn * 256 + h * 128;
                ob[lane]      = v0 * HSCALE;
                ob[lane + 32] = v1 * HSCALE;
                ob[lane + 64] = v2 * HSCALE;
                ob[lane + 96] = v3 * HSCALE;
            }
        }
    }
}

__global__ void write_end(float* __restrict__ eout, const int* __restrict__ sp)
{
    *eout = (float)(*sp + S_LEN);
}

// =====================================================================
typedef CUresult (*EncodeFn)(CUtensorMap*, CUtensorMapDataType, cuuint32_t, void*,
                             const cuuint64_t*, const cuuint64_t*, const cuuint32_t*,
                             const cuuint32_t*, CUtensorMapInterleave, CUtensorMapSwizzle,
                             CUtensorMapL2promotion, CUtensorMapFloatOOBfill);

static void make_map(EncodeFn enc, CUtensorMap* m, void* base, int K, int R, int boxR)
{
    cuuint64_t dims[3]    = {(cuuint64_t)K, (cuuint64_t)R, 1};
    cuuint64_t strides[2] = {(cuuint64_t)K * 2, (cuuint64_t)K * 2 * (cuuint64_t)R};
    cuuint32_t box[3]     = {64, (cuuint32_t)boxR, 1};
    cuuint32_t es[3]      = {1, 1, 1};
    enc(m, CU_TENSOR_MAP_DATA_TYPE_BFLOAT16, 3, base, dims, strides, box, es,
        CU_TENSOR_MAP_INTERLEAVE_NONE, CU_TENSOR_MAP_SWIZZLE_128B,
        CU_TENSOR_MAP_L2_PROMOTION_L2_128B, CU_TENSOR_MAP_FLOAT_OOB_FILL_NONE);
}

extern "C" void kernel_launch(void* const* d_in, const int* in_sizes, int n_in,
                              void* d_out, int out_size)
{
    const float* x   = (const float*)d_in[0];
    const float* qr  = (const float*)d_in[1];
    const float* fc  = (const float*)d_in[2];
    const float* fs  = (const float*)d_in[3];
    const float* wqb = (const float*)d_in[4];
    const float* wk  = (const float*)d_in[5];
    const float* kg  = (const float*)d_in[6];
    const float* kb  = (const float*)d_in[7];
    const float* wp  = (const float*)d_in[8];
    const int*   sp  = (const int*)d_in[9];

    float* out  = (float*)d_out;
    float* qout = out;
    float* wout = out + QN;
    float* kout = out + QN + WN;
    float* eout = out + QN + WN + KN;

    void *qrh, *qrl, *wqh, *wql, *xh, *xl, *wbh, *wbl;
    cudaGetSymbolAddress(&qrh, g_qr_h);
    cudaGetSymbolAddress(&qrl, g_qr_l);
    cudaGetSymbolAddress(&wqh, g_wq_h);
    cudaGetSymbolAddress(&wql, g_wq_l);
    cudaGetSymbolAddress(&xh,  g_x_h);
    cudaGetSymbolAddress(&xl,  g_x_l);
    cudaGetSymbolAddress(&wbh, g_wb_h);
    cudaGetSymbolAddress(&wbl, g_wb_l);

    EncodeFn enc = nullptr;
    cudaDriverEntryPointQueryResult qres;
    cudaGetDriverEntryPoint("cuTensorMapEncodeTiled", (void**)&enc, cudaEnableDefault, &qres);

    CUtensorMap mQAh, mQAl, mQBh, mQBl, mPAh, mPAl, mPBh, mPBl;
    make_map(enc, &mQAh, qrh, LORA, NROWS, 128);
    make_map(enc, &mQAl, qrl, LORA, NROWS, 128);
    make_map(enc, &mQBh, wqh, LORA, NROWS, 256);
    make_map(enc, &mQBl, wql, LORA, NROWS, 256);
    make_map(enc, &mPAh, xh,  D_IN, NROWS, 128);
    make_map(enc, &mPAl, xl,  D_IN, NROWS, 128);
    make_map(enc, &mPBh, wbh, D_IN, 256, 256);
    make_map(enc, &mPBl, wbl, D_IN, 256, 256);

    cudaFuncSetAttribute(fused_gemm, cudaFuncAttributeMaxDynamicSharedMemorySize, SMEM_TOT);

    prep_all<<<(PREP_TOTAL + 255) / 256, 256>>>(
        (const float4*)qr, (const float4*)wqb, (const float4*)x, wk, wp);

    fused_gemm<<<2112, 256, SMEM_TOT>>>(
        mQAh, mQAl, mQBh, mQBl, mPAh, mPAl, mPBh, mPBl,
        qout, kout, wout, fc, fs, kg, kb);

    write_end<<<1, 1>>>(eout, sp);
}